// round 1
// baseline (speedup 1.0000x reference)
#include <cuda_runtime.h>

// RecurTreeGen: 12-level binary Tree-LSTM reduction.
// Each level: A = H_in viewed [m,256] (reshape of [2m,128]),
//             P[m,640] = A @ W  (W = [U_iou | Uf_W] packed, 256x640),
//             i,o,u,f1,f2 gates -> c = i*u + f1*cl + f2*cr, h = o*tanh(c).
// fp32 exact math; FFMA2 (fma.rn.f32x2) packed fp32 for 2 FLOP/lane/instr.

#define NSTATES0 262144     // 64 graphs * 4096 leaves
#define MAXM     131072     // outputs at level 0
#define NLEVELS  12

typedef unsigned long long ull;

// Scratch (static __device__ globals per allocation rules)
__device__ __align__(16) float g_W[256 * 640];
__device__ __align__(16) float g_b[640];
__device__ __align__(16) float g_h[2][MAXM * 128];
__device__ __align__(16) float g_c[2][MAXM * 128];

__global__ void pack_weights(const float* __restrict__ U_iou,
                             const float* __restrict__ b_iou,
                             const float* __restrict__ Uf_W,
                             const float* __restrict__ Uf_b) {
    int idx = blockIdx.x * blockDim.x + threadIdx.x;
    int stride = gridDim.x * blockDim.x;
    for (int i = idx; i < 256 * 640; i += stride) {
        int k = i / 640, c = i - k * 640;
        g_W[i] = (c < 384) ? U_iou[k * 384 + c] : Uf_W[k * 256 + (c - 384)];
    }
    if (idx < 640)
        g_b[idx] = (idx < 384) ? b_iou[idx] : Uf_b[idx - 384];
}

__device__ __forceinline__ ull pack2(float lo, float hi) {
    ull r;
    asm("mov.b64 %0, {%1, %2};" : "=l"(r) : "f"(lo), "f"(hi));
    return r;
}
__device__ __forceinline__ void unpack2(ull v, float& lo, float& hi) {
    asm("mov.b64 {%0, %1}, %2;" : "=f"(lo), "=f"(hi) : "l"(v));
}
__device__ __forceinline__ void ffma2(ull& d, ull a, ull b) {
    asm("fma.rn.f32x2 %0, %1, %2, %0;" : "+l"(d) : "l"(a), "l"(b));
}

__device__ __forceinline__ float sigmoidf(float x) {
    return 1.0f / (1.0f + expf(-x));
}

// CTA tile: 64 rows x 32 features (=160 preact cols across 5 gates).
// 256 threads as (tx 0..15, ty 0..15); thread tile: 4 rows x (2 features x 5 gates).
__global__ __launch_bounds__(256)
void level_kernel(const float* __restrict__ h0,
                  const float* __restrict__ c0,
                  float* __restrict__ out,
                  int level, int m) {
    const float* A;
    const float* C;
    if (level == 0) { A = h0; C = c0; }
    else { A = g_h[(level - 1) & 1]; C = g_c[(level - 1) & 1]; }
    float* Hout = g_h[level & 1];
    float* Cout = g_c[level & 1];
    const bool last = (level == NLEVELS - 1);

    __shared__ float As[64][20];    // 16-wide k chunk, padded for bank/align
    __shared__ float Ws[16][162];   // k chunk x 160 cols, padded (even stride for 8B align)

    const int tid = threadIdx.x;
    const int tx = tid & 15;
    const int ty = tid >> 4;
    const int bm = blockIdx.x;   // 64-row block
    const int gy = blockIdx.y;   // feature group: j in [gy*32, gy*32+32)
    const int rowbase = bm * 64;

    ull acc[4][5];
#pragma unroll
    for (int r = 0; r < 4; r++)
#pragma unroll
        for (int g = 0; g < 5; g++) acc[r][g] = 0ull;

    const float* Arow = A + (size_t)rowbase * 256;
    const int a_r = tid >> 2;            // row this thread loads
    const int a_q = (tid & 3) * 4;       // float4 slot within 16-k chunk
    const int w_kk = tid >> 4;           // Ws row this thread fills
    const int w_c0 = tid & 15;

    for (int kc = 0; kc < 256; kc += 16) {
        // --- load A chunk: 64 rows x 16 k (one float4 per thread) ---
        {
            float4 v = *(const float4*)&Arow[a_r * 256 + kc + a_q];
            *(float4*)&As[a_r][a_q] = v;
        }
        // --- load W chunk: 16 k x 160 cols ---
#pragma unroll
        for (int t = 0; t < 10; t++) {
            int c = w_c0 + t * 16;           // 0..159
            int g = c >> 5;
            int jl = c & 31;
            Ws[w_kk][c] = g_W[(kc + w_kk) * 640 + g * 128 + gy * 32 + jl];
        }
        __syncthreads();

#pragma unroll
        for (int kk = 0; kk < 16; kk++) {
            ull a2[4];
#pragma unroll
            for (int r = 0; r < 4; r++) {
                float a = As[ty * 4 + r][kk];
                a2[r] = pack2(a, a);
            }
#pragma unroll
            for (int g = 0; g < 5; g++) {
                ull w2 = *(const ull*)&Ws[kk][g * 32 + 2 * tx];
#pragma unroll
                for (int r = 0; r < 4; r++) ffma2(acc[r][g], a2[r], w2);
            }
        }
        __syncthreads();
    }

    // --- fused LSTM epilogue ---
    const int jj = gy * 32 + 2 * tx;   // first of this thread's feature pair
    const float2 bi  = *(const float2*)&g_b[0 * 128 + jj];
    const float2 bo  = *(const float2*)&g_b[1 * 128 + jj];
    const float2 bu  = *(const float2*)&g_b[2 * 128 + jj];
    const float2 bf1 = *(const float2*)&g_b[3 * 128 + jj];
    const float2 bf2 = *(const float2*)&g_b[4 * 128 + jj];

#pragma unroll
    for (int r = 0; r < 4; r++) {
        const int R = rowbase + ty * 4 + r;
        float pi0, pi1, po0, po1, pu0, pu1, pf10, pf11, pf20, pf21;
        unpack2(acc[r][0], pi0, pi1);
        unpack2(acc[r][1], po0, po1);
        unpack2(acc[r][2], pu0, pu1);
        unpack2(acc[r][3], pf10, pf11);
        unpack2(acc[r][4], pf20, pf21);

        float iv0 = sigmoidf(pi0 + bi.x),  iv1 = sigmoidf(pi1 + bi.y);
        float ov0 = sigmoidf(po0 + bo.x),  ov1 = sigmoidf(po1 + bo.y);
        float uv0 = tanhf(pu0 + bu.x),     uv1 = tanhf(pu1 + bu.y);
        float f10 = sigmoidf(pf10 + bf1.x), f11 = sigmoidf(pf11 + bf1.y);
        float f20 = sigmoidf(pf20 + bf2.x), f21 = sigmoidf(pf21 + bf2.y);

        float2 cl = *(const float2*)&C[(size_t)R * 256 + jj];
        float2 cr = *(const float2*)&C[(size_t)R * 256 + 128 + jj];

        float cn0 = iv0 * uv0 + f10 * cl.x + f20 * cr.x;
        float cn1 = iv1 * uv1 + f11 * cl.y + f21 * cr.y;
        float hn0 = ov0 * tanhf(cn0);
        float hn1 = ov1 * tanhf(cn1);

        if (last) {
            // out[b, 0:128] = h_root, out[b, 128:256] = c_root
            *(float2*)&out[(size_t)R * 256 + jj] = make_float2(hn0, hn1);
            *(float2*)&out[(size_t)R * 256 + 128 + jj] = make_float2(cn0, cn1);
        } else {
            *(float2*)&Hout[(size_t)R * 128 + jj] = make_float2(hn0, hn1);
            *(float2*)&Cout[(size_t)R * 128 + jj] = make_float2(cn0, cn1);
        }
    }
}

extern "C" void kernel_launch(void* const* d_in, const int* in_sizes, int n_in,
                              void* d_out, int out_size) {
    const float* h_bot = (const float*)d_in[0];
    const float* c_bot = (const float*)d_in[1];
    const float* U_iou = (const float*)d_in[2];
    const float* b_iou = (const float*)d_in[3];
    const float* Uf_W  = (const float*)d_in[4];
    const float* Uf_b  = (const float*)d_in[5];
    float* out = (float*)d_out;

    pack_weights<<<160, 256>>>(U_iou, b_iou, Uf_W, Uf_b);

    int nstates = NSTATES0;
    for (int l = 0; l < NLEVELS; l++) {
        int m = nstates >> 1;
        dim3 grid(m / 64, 4);
        level_kernel<<<grid, 256>>>(h_bot, c_bot, out, l, m);
        nstates = m;
    }
}

// round 4
// speedup vs baseline: 2.1973x; 2.1973x over previous
#include <cuda_runtime.h>
#include <cuda_bf16.h>
#include <cstdint>

// RecurTreeGen: 12-level Tree-LSTM reduction via warp-level bf16 mma.sync (HMMA).
// Level l: A = H_prev viewed [m,256]; P[m,640] = A @ W; fused LSTM cell.
// 3-term bf16 split (Ah*Wh + Ah*Wl + Al*Wh), fp32 register accumulation.
// A stored in mma A-fragment layout in global (written by prior epilogue);
// W pre-packed in B-fragment layout (L2-resident).

#define NLEVELS 12
#define SMEM_BYTES 104448   // 3*18432 stage ring / 88064 Ps overlay + 16384 hstage

// ---------------- device scratch (static; no allocation) ----------------
__device__ uint4 g_AfH[2][(size_t)8192 * 16 * 32];   // [buf][ (mtG*16+kt)*32+lane ]
__device__ uint4 g_AfL[2][(size_t)8192 * 16 * 32];
__device__ __align__(16) float g_cb[2][(size_t)131072 * 128];
__device__ uint2 g_WfH[40960];   // [ (gy*16+kt)*640 + nt*32+lane ]
__device__ uint2 g_WfL[40960];

// ---------------- helpers ----------------
__device__ __forceinline__ uint32_t smem_u32(const void* p) {
    uint32_t a;
    asm("{ .reg .u64 t; cvta.to.shared.u64 t, %1; cvt.u32.u64 %0, t; }"
        : "=r"(a) : "l"(p));
    return a;
}
__device__ __forceinline__ void cp16(uint32_t d, const void* s) {
    asm volatile("cp.async.cg.shared.global [%0],[%1],16;" :: "r"(d), "l"(s) : "memory");
}
__device__ __forceinline__ void cp8(uint32_t d, const void* s) {
    asm volatile("cp.async.ca.shared.global [%0],[%1],8;" :: "r"(d), "l"(s) : "memory");
}
#define CP_COMMIT() asm volatile("cp.async.commit_group;" ::: "memory")
#define CP_WAIT1()  asm volatile("cp.async.wait_group 1;" ::: "memory")

__device__ __forceinline__ void split2(float x, float y, uint32_t& hi, uint32_t& lo) {
    __nv_bfloat162 h = __floats2bfloat162_rn(x, y);
    float rx = x - __bfloat162float(h.x);
    float ry = y - __bfloat162float(h.y);
    __nv_bfloat162 l = __floats2bfloat162_rn(rx, ry);
    hi = *reinterpret_cast<uint32_t*>(&h);
    lo = *reinterpret_cast<uint32_t*>(&l);
}
__device__ __forceinline__ void mma16816(float* d, const uint32_t* a, const uint32_t* b) {
    asm volatile(
        "mma.sync.aligned.m16n8k16.row.col.f32.bf16.bf16.f32 "
        "{%0,%1,%2,%3}, {%4,%5,%6,%7}, {%8,%9}, {%0,%1,%2,%3};"
        : "+f"(d[0]), "+f"(d[1]), "+f"(d[2]), "+f"(d[3])
        : "r"(a[0]), "r"(a[1]), "r"(a[2]), "r"(a[3]), "r"(b[0]), "r"(b[1]));
}

__device__ __forceinline__ float sigf(float x) {
    return 1.0f / (1.0f + __expf(-x));
}
__device__ __forceinline__ float tanhfast(float x) {
    return __fdividef(2.0f, 1.0f + __expf(-2.0f * x)) - 1.0f;
}
__device__ __forceinline__ void cell1(float pi, float po, float pu, float pf1, float pf2,
                                      float bi, float bo, float bu, float b1, float b2,
                                      float cl, float crv, float& h, float& c) {
    float iv = sigf(pi + bi), ov = sigf(po + bo), uv = tanhfast(pu + bu);
    float f1 = sigf(pf1 + b1), f2 = sigf(pf2 + b2);
    c = iv * uv + f1 * cl + f2 * crv;
    h = ov * tanhfast(c);
}

// ---------------- W pack: fp32 -> bf16 hi/lo in B-fragment layout ----------------
// chunk gy (0..3): 160 cols c = gate*32+feat, j = gy*32+feat; frag n = nt*8+(lane>>2),
// k = kt*16 + (lane&3)*2 (+{0,1} low pair, +8 high pair).
__global__ void pack_w(const float* __restrict__ U_iou, const float* __restrict__ Uf_W) {
    int idx = blockIdx.x * 256 + threadIdx.x;   // < 40960
    int gy = idx / 10240;
    int rem = idx % 10240;
    int kt = rem / 640;
    int f = rem % 640;
    int nt = f >> 5;
    int lane = f & 31;
    int c = nt * 8 + (lane >> 2);
    int gate = c >> 5, feat = c & 31;
    int j = gy * 32 + feat;
    int k0 = kt * 16 + (lane & 3) * 2;

    float w0, w1, w2, w3;
    if (gate < 3) {
        w0 = U_iou[(k0 + 0) * 384 + gate * 128 + j];
        w1 = U_iou[(k0 + 1) * 384 + gate * 128 + j];
        w2 = U_iou[(k0 + 8) * 384 + gate * 128 + j];
        w3 = U_iou[(k0 + 9) * 384 + gate * 128 + j];
    } else {
        w0 = Uf_W[(k0 + 0) * 256 + (gate - 3) * 128 + j];
        w1 = Uf_W[(k0 + 1) * 256 + (gate - 3) * 128 + j];
        w2 = Uf_W[(k0 + 8) * 256 + (gate - 3) * 128 + j];
        w3 = Uf_W[(k0 + 9) * 256 + (gate - 3) * 128 + j];
    }
    uint2 hi, lo;
    split2(w0, w1, hi.x, lo.x);
    split2(w2, w3, hi.y, lo.y);
    g_WfH[idx] = hi;
    g_WfL[idx] = lo;
}

// ---------------- level-0 A convert: h_bot [131072,256] -> frag layout ----------------
__global__ void conv_a(const float* __restrict__ hb) {
    int wid = threadIdx.x >> 5, lane = threadIdx.x & 31;
    int tile = blockIdx.x * 8 + wid;                 // < 131072 (mtG*16+kt)
    const float* base = hb + (size_t)(tile >> 4) * 16 * 256 + (tile & 15) * 16;
    int r = lane >> 2, kq = (lane & 3) * 2;
    float2 v00 = *(const float2*)(base + (r + 0) * 256 + kq + 0);
    float2 v10 = *(const float2*)(base + (r + 8) * 256 + kq + 0);
    float2 v01 = *(const float2*)(base + (r + 0) * 256 + kq + 8);
    float2 v11 = *(const float2*)(base + (r + 8) * 256 + kq + 8);
    uint4 hi, lo;
    split2(v00.x, v00.y, hi.x, lo.x);
    split2(v10.x, v10.y, hi.y, lo.y);
    split2(v01.x, v01.y, hi.z, lo.z);
    split2(v11.x, v11.y, hi.w, lo.w);
    g_AfH[0][(size_t)tile * 32 + lane] = hi;
    g_AfL[0][(size_t)tile * 32 + lane] = lo;
}

// ---------------- GEMM + fused cell ----------------
// Grid: ( (m+127)/128, 4 ); 256 threads (8 warps: wm=wid>>1 in 0..3, wn=wid&1).
// SMEM stages: [stage][ A: 2 terms x 8mt x 32lane x 16B = 8192 | B: 2 terms x 20nt x 32 x 8B = 10240 ]
__global__ void __launch_bounds__(256)
gemm_level(const float* __restrict__ c_bot,
           const float* __restrict__ b_iou, const float* __restrict__ Uf_b,
           float* __restrict__ out, int level, int m) {
    extern __shared__ char smem[];
    const uint32_t sb = smem_u32(smem);
    const int tid = threadIdx.x, wid = tid >> 5, lane = tid & 31;
    const int wm = wid >> 1, wn = wid & 1;
    const int rb = blockIdx.x, gy = blockIdx.y;
    const int rowbase = rb * 128;
    const bool last = (level == NLEVELS - 1);
    const int rd = level & 1, wb = (level + 1) & 1;
    const uint4* AH = g_AfH[rd];
    const uint4* AL = g_AfL[rd];
    const float* Cin = (level == 0) ? c_bot : g_cb[(level + 1) & 1];

    float acc[2][10][4];
#pragma unroll
    for (int a = 0; a < 2; a++)
#pragma unroll
        for (int i = 0; i < 10; i++)
#pragma unroll
            for (int q = 0; q < 4; q++) acc[a][i][q] = 0.0f;

    // producer
    auto issue = [&](int s, int kt) {
        uint32_t dstA = sb + s * 18432 + tid * 16;
        size_t ai = ((size_t)(rb * 8 + wid) * 16 + kt) * 32 + lane;
        cp16(dstA, AH + ai);
        cp16(dstA + 4096, AL + ai);
        int basef = (gy * 16 + kt) * 640;
#pragma unroll
        for (int f0 = 0; f0 < 3; f0++) {
            int f = tid + f0 * 256;
            if (f < 640) {
                uint32_t dstB = sb + s * 18432 + 8192 + f * 8;
                cp8(dstB, g_WfH + basef + f);
                cp8(dstB + 5120, g_WfL + basef + f);
            }
        }
    };

    issue(0, 0); CP_COMMIT();
    issue(1, 1); CP_COMMIT();

    for (int kt = 0; kt < 16; kt++) {
        CP_WAIT1();
        __syncthreads();
        if (kt + 2 < 16) issue((kt + 2) % 3, kt + 2);
        CP_COMMIT();

        const int s = kt % 3;
        const char* stg = smem + s * 18432;
        uint4 AHf[2], ALf[2];
#pragma unroll
        for (int t = 0; t < 2; t++) {
            AHf[t] = *(const uint4*)(stg + (wm * 2 + t) * 512 + lane * 16);
            ALf[t] = *(const uint4*)(stg + 4096 + (wm * 2 + t) * 512 + lane * 16);
        }
        uint2 BH[10], BL[10];
#pragma unroll
        for (int i = 0; i < 10; i++) {
            int off = 8192 + ((wn * 10 + i) * 32 + lane) * 8;
            BH[i] = *(const uint2*)(stg + off);
            BL[i] = *(const uint2*)(stg + off + 5120);
        }
#pragma unroll
        for (int t = 0; t < 2; t++)
#pragma unroll
            for (int i = 0; i < 10; i++) {
                mma16816(acc[t][i], (const uint32_t*)&AHf[t], (const uint32_t*)&BH[i]);
                mma16816(acc[t][i], (const uint32_t*)&AHf[t], (const uint32_t*)&BL[i]);
                mma16816(acc[t][i], (const uint32_t*)&ALf[t], (const uint32_t*)&BH[i]);
            }
    }
    __syncthreads();

    // --- stage preacts to smem: Ps[128][172] fp32 ---
    float* Ps = (float*)smem;
    {
        const int prow = wm * 32 + (lane >> 2);
        const int pcol = wn * 80 + (lane & 3) * 2;
#pragma unroll
        for (int t = 0; t < 2; t++)
#pragma unroll
            for (int i = 0; i < 10; i++) {
                int rr0 = prow + t * 16;
                int cc = pcol + i * 8;
                *(float2*)&Ps[(rr0 + 0) * 172 + cc] = make_float2(acc[t][i][0], acc[t][i][1]);
                *(float2*)&Ps[(rr0 + 8) * 172 + cc] = make_float2(acc[t][i][2], acc[t][i][3]);
            }
    }
    __syncthreads();

    // --- fused LSTM cell + outputs ---
    uint32_t* sHi = (uint32_t*)(smem + 88064);
    uint32_t* sLo = (uint32_t*)(smem + 96256);
    const int r = tid >> 1, fh = tid & 1;
    const int R = rowbase + r;
    if (R < m) {
        const int j0 = gy * 32 + fh * 16;
        float hr[16], cr_[16];
#pragma unroll
        for (int q = 0; q < 4; q++) {
            int cb = fh * 16 + q * 4;
            float4 pi  = *(const float4*)&Ps[r * 172 + 0 * 32 + cb];
            float4 po  = *(const float4*)&Ps[r * 172 + 1 * 32 + cb];
            float4 pu  = *(const float4*)&Ps[r * 172 + 2 * 32 + cb];
            float4 pf1 = *(const float4*)&Ps[r * 172 + 3 * 32 + cb];
            float4 pf2 = *(const float4*)&Ps[r * 172 + 4 * 32 + cb];
            int j = j0 + q * 4;
            float4 bi  = *(const float4*)(b_iou + 0 + j);
            float4 bo  = *(const float4*)(b_iou + 128 + j);
            float4 bu  = *(const float4*)(b_iou + 256 + j);
            float4 bf1 = *(const float4*)(Uf_b + 0 + j);
            float4 bf2 = *(const float4*)(Uf_b + 128 + j);
            float4 cl  = *(const float4*)(Cin + (size_t)R * 256 + j);
            float4 crv = *(const float4*)(Cin + (size_t)R * 256 + 128 + j);

            float4 hv, cv;
            cell1(pi.x, po.x, pu.x, pf1.x, pf2.x, bi.x, bo.x, bu.x, bf1.x, bf2.x, cl.x, crv.x, hv.x, cv.x);
            cell1(pi.y, po.y, pu.y, pf1.y, pf2.y, bi.y, bo.y, bu.y, bf1.y, bf2.y, cl.y, crv.y, hv.y, cv.y);
            cell1(pi.z, po.z, pu.z, pf1.z, pf2.z, bi.z, bo.z, bu.z, bf1.z, bf2.z, cl.z, crv.z, hv.z, cv.z);
            cell1(pi.w, po.w, pu.w, pf1.w, pf2.w, bi.w, bo.w, bu.w, bf1.w, bf2.w, cl.w, crv.w, hv.w, cv.w);

            hr[q * 4 + 0] = hv.x; hr[q * 4 + 1] = hv.y; hr[q * 4 + 2] = hv.z; hr[q * 4 + 3] = hv.w;
            cr_[q * 4 + 0] = cv.x; cr_[q * 4 + 1] = cv.y; cr_[q * 4 + 2] = cv.z; cr_[q * 4 + 3] = cv.w;

            if (last) {
                *(float4*)(out + (size_t)R * 256 + j) = hv;
                *(float4*)(out + (size_t)R * 256 + 128 + j) = cv;
            } else {
                *(float4*)(&g_cb[level & 1][(size_t)R * 128 + j]) = cv;
            }
        }
        if (!last) {
            // h -> next-level A fragment staging in smem
            const int mtl = r >> 5;
            const int rr = (r >> 1) & 15;
            const int ktl = (r & 1) * 2 + fh;
#pragma unroll
            for (int p = 0; p < 8; p++) {
                uint32_t h32, l32;
                split2(hr[2 * p], hr[2 * p + 1], h32, l32);
                int idxu = ((mtl * 4 + ktl) * 32 + ((rr & 7) * 4 + (p & 3))) * 4
                         + ((rr >> 3) + 2 * (p >> 2));
                sHi[idxu] = h32;
                sLo[idxu] = l32;
            }
        }
    }
    __syncthreads();
    if (!last) {
        uint4* dH = g_AfH[wb];
        uint4* dL = g_AfL[wb];
#pragma unroll
        for (int c0 = 0; c0 < 2; c0++) {
            int c = tid + c0 * 256;                 // < 512 uint4 units
            int mtl = c >> 7, ktl = (c >> 5) & 3, lu = c & 31;
            int ktg = (ktl >> 1) * 8 + gy * 2 + (ktl & 1);
            int mtG = rb * 4 + mtl;
            size_t di = ((size_t)mtG * 16 + ktg) * 32 + lu;
            dH[di] = ((const uint4*)sHi)[c];
            dL[di] = ((const uint4*)sLo)[c];
        }
    }
}

extern "C" void kernel_launch(void* const* d_in, const int* in_sizes, int n_in,
                              void* d_out, int out_size) {
    const float* h_bot = (const float*)d_in[0];
    const float* c_bot = (const float*)d_in[1];
    const float* U_iou = (const float*)d_in[2];
    const float* b_iou = (const float*)d_in[3];
    const float* Uf_W  = (const float*)d_in[4];
    const float* Uf_b  = (const float*)d_in[5];
    float* out = (float*)d_out;

    cudaFuncSetAttribute(gemm_level, cudaFuncAttributeMaxDynamicSharedMemorySize,
                         SMEM_BYTES);

    pack_w<<<160, 256>>>(U_iou, Uf_W);
    conv_a<<<16384, 256>>>(h_bot);

    int nstates = 262144;
    for (int l = 0; l < NLEVELS; l++) {
        int m = nstates >> 1;                    // output rows this level
        dim3 grid((m + 127) / 128, 4);
        gemm_level<<<grid, 256, SMEM_BYTES>>>(c_bot, b_iou, Uf_b, out, l, m);
        nstates = m;
    }
}